// round 1
// baseline (speedup 1.0000x reference)
#include <cuda_runtime.h>
#include <math.h>

// ---------------------------------------------------------------------------
// RotarySelfAttention: x[B,T,C] -> QKV GEMM -> RoPE -> attention -> out proj
// B=2, T=2048, C=1024, H=16, D=64
// ---------------------------------------------------------------------------

namespace {

constexpr int B_   = 2;
constexpr int T_   = 2048;
constexpr int C_   = 1024;
constexpr int NH   = 16;
constexpr int HD   = 64;
constexpr int MTOK = B_ * T_;   // 4096

// Scratch (allocation-free rule: __device__ globals)
__device__ float g_qkv[(size_t)MTOK * 3 * C_];     // [B*T, 3C]
__device__ float g_q[(size_t)B_ * NH * T_ * HD];   // [B,H,T,D] (pre-scaled)
__device__ float g_k[(size_t)B_ * NH * T_ * HD];
__device__ float g_v[(size_t)B_ * NH * T_ * HD];
__device__ float g_ctx[(size_t)MTOK * C_];         // [B,T,C]

// ---------------------------------------------------------------------------
// SGEMM: C[M,N] = A[M,K] @ B[K,N] + bias[N]   (row-major, all dims %128/%8==0)
// 128x128 block tile, BK=8, 256 threads, 8x8 per thread.
// ---------------------------------------------------------------------------
__global__ __launch_bounds__(256)
void sgemm_bias_kernel(const float* __restrict__ A,
                       const float* __restrict__ Bm,
                       const float* __restrict__ bias,
                       float* __restrict__ Cout,
                       int M, int N, int K)
{
    constexpr int BM = 128, BN = 128, BK = 8, TM = 8, TN = 8;
    __shared__ float As[BK][BM];
    __shared__ float Bs[BK][BN];

    const int tid  = threadIdx.x;
    const int brow = blockIdx.y * BM;
    const int bcol = blockIdx.x * BN;

    // global load mapping
    const int aRow = tid >> 1;          // 0..127
    const int aCol = (tid & 1) << 2;    // 0 or 4
    const int bRow = tid >> 5;          // 0..7
    const int bCol = (tid & 31) << 2;   // 0..124

    // compute mapping
    const int tRow = (tid >> 4) * TM;   // 0..120
    const int tCol = (tid & 15) * TN;   // 0..120

    float acc[TM][TN];
#pragma unroll
    for (int i = 0; i < TM; i++)
#pragma unroll
        for (int j = 0; j < TN; j++) acc[i][j] = 0.f;

    for (int k0 = 0; k0 < K; k0 += BK) {
        float4 a4 = *(const float4*)(A  + (size_t)(brow + aRow) * K + k0 + aCol);
        float4 b4 = *(const float4*)(Bm + (size_t)(k0 + bRow) * N + bcol + bCol);
        As[aCol + 0][aRow] = a4.x;
        As[aCol + 1][aRow] = a4.y;
        As[aCol + 2][aRow] = a4.z;
        As[aCol + 3][aRow] = a4.w;
        *(float4*)&Bs[bRow][bCol] = b4;
        __syncthreads();

#pragma unroll
        for (int kk = 0; kk < BK; kk++) {
            float ar[TM], br[TN];
#pragma unroll
            for (int i = 0; i < TM; i += 4)
                *(float4*)&ar[i] = *(const float4*)&As[kk][tRow + i];
#pragma unroll
            for (int j = 0; j < TN; j += 4)
                *(float4*)&br[j] = *(const float4*)&Bs[kk][tCol + j];
#pragma unroll
            for (int i = 0; i < TM; i++)
#pragma unroll
                for (int j = 0; j < TN; j++)
                    acc[i][j] += ar[i] * br[j];
        }
        __syncthreads();
    }

#pragma unroll
    for (int i = 0; i < TM; i++) {
        float* crow = Cout + (size_t)(brow + tRow + i) * N + bcol + tCol;
#pragma unroll
        for (int j = 0; j < TN; j += 4) {
            float4 o;
            o.x = acc[i][j + 0] + bias[bcol + tCol + j + 0];
            o.y = acc[i][j + 1] + bias[bcol + tCol + j + 1];
            o.z = acc[i][j + 2] + bias[bcol + tCol + j + 2];
            o.w = acc[i][j + 3] + bias[bcol + tCol + j + 3];
            *(float4*)(crow + j) = o;
        }
    }
}

// ---------------------------------------------------------------------------
// RoPE + split qkv[B*T,3C] -> q,k,v in [B,H,T,D]. q is pre-scaled by D^-0.5.
// One thread per (b,h,t,d-pair), d in [0,32).
// ---------------------------------------------------------------------------
__global__ __launch_bounds__(256)
void rope_split_kernel(const float* __restrict__ qkv,
                       float* __restrict__ q,
                       float* __restrict__ k,
                       float* __restrict__ v)
{
    const int idx = blockIdx.x * blockDim.x + threadIdx.x;
    const int d = idx & 31;
    const int t = (idx >> 5) & (T_ - 1);
    const int h = (idx >> 16) & (NH - 1);
    const int b = idx >> 20;

    const float* base = qkv + (size_t)(b * T_ + t) * (3 * C_) + h * HD + d;
    const float q1 = base[0],       q2 = base[32];
    const float k1 = base[C_],      k2 = base[C_ + 32];
    const float v1 = base[2 * C_],  v2 = base[2 * C_ + 32];

    // inv_freq = 10000^(-d/32) ; angle = t * inv_freq  (all fp32 like the ref)
    const float inv_freq = expf((float)d * -0.28782313662425574f); // ln(1e4)/32
    const float ang = (float)t * inv_freq;
    float s, c;
    sincosf(ang, &s, &c);

    const float scale = 0.125f; // HD^-0.5
    const size_t o = ((size_t)(b * NH + h) * T_ + t) * HD + d;
    q[o]      = (q1 * c - q2 * s) * scale;
    q[o + 32] = (q2 * c + q1 * s) * scale;
    k[o]      = k1 * c - k2 * s;
    k[o + 32] = k2 * c + k1 * s;
    v[o]      = v1;
    v[o + 32] = v2;
}

// ---------------------------------------------------------------------------
// Flash attention (fp32, non-causal). One query row per thread.
// Block = 128 threads = 128 query rows of one (b,h). K/V tiles of 32 rows.
// Static smem: Ks 8KB + Vs 8KB + scores 16KB = 32KB.
// ---------------------------------------------------------------------------
constexpr int QB = 128;  // queries per block (== blockDim.x)
constexpr int KB = 32;   // keys per tile

__global__ __launch_bounds__(QB)
void flash_attn_kernel(const float* __restrict__ q,
                       const float* __restrict__ k,
                       const float* __restrict__ v,
                       float* __restrict__ ctx)
{
    __shared__ float Ks[KB * HD];
    __shared__ float Vs[KB * HD];
    __shared__ float Ssc[KB * QB];   // transposed scores: Ssc[j*QB + tid]

    const int tid  = threadIdx.x;
    const int bh   = blockIdx.y;            // b*NH + h
    const int b    = bh >> 4;
    const int h    = bh & 15;
    const int qrow = blockIdx.x * QB + tid;

    const float NEG_INF = __int_as_float(0xff800000u);

    const float* qptr = q + ((size_t)bh * T_ + qrow) * HD;
    float qr[HD];
#pragma unroll
    for (int d = 0; d < HD; d += 4) {
        float4 t4 = *(const float4*)(qptr + d);
        qr[d] = t4.x; qr[d + 1] = t4.y; qr[d + 2] = t4.z; qr[d + 3] = t4.w;
    }

    float acc[HD];
#pragma unroll
    for (int d = 0; d < HD; d++) acc[d] = 0.f;
    float mrun = NEG_INF;
    float lrun = 0.f;

    const float* kbase = k + (size_t)bh * T_ * HD;
    const float* vbase = v + (size_t)bh * T_ * HD;

    for (int k0 = 0; k0 < T_; k0 += KB) {
        __syncthreads();   // previous tile fully consumed before overwrite
        // load K/V tile: KB*HD = 2048 floats each; 4 float4 per thread
#pragma unroll
        for (int i = 0; i < (KB * HD) / (QB * 4); i++) {
            const int off = (i * QB + tid) * 4;
            *(float4*)&Ks[off] = *(const float4*)&kbase[(size_t)k0 * HD + off];
            *(float4*)&Vs[off] = *(const float4*)&vbase[(size_t)k0 * HD + off];
        }
        __syncthreads();

        // pass A: scores + tile max
        float tmax = NEG_INF;
#pragma unroll 2
        for (int j = 0; j < KB; j++) {
            float s = 0.f;
#pragma unroll
            for (int d = 0; d < HD; d++) s += qr[d] * Ks[j * HD + d];
            Ssc[j * QB + tid] = s;
            tmax = fmaxf(tmax, s);
        }

        const float mnew  = fmaxf(mrun, tmax);
        const float alpha = __expf(mrun - mnew);   // exp(-inf)=0 on first tile
        lrun *= alpha;
#pragma unroll
        for (int d = 0; d < HD; d++) acc[d] *= alpha;
        mrun = mnew;

        // pass B: probabilities + PV accumulate
#pragma unroll 2
        for (int j = 0; j < KB; j++) {
            const float p = __expf(Ssc[j * QB + tid] - mnew);
            lrun += p;
#pragma unroll
            for (int d = 0; d < HD; d++) acc[d] += p * Vs[j * HD + d];
        }
    }

    const float inv_l = 1.f / lrun;
    float* optr = ctx + ((size_t)b * T_ + qrow) * C_ + h * HD;
#pragma unroll
    for (int d = 0; d < HD; d += 4) {
        float4 o;
        o.x = acc[d + 0] * inv_l;
        o.y = acc[d + 1] * inv_l;
        o.z = acc[d + 2] * inv_l;
        o.w = acc[d + 3] * inv_l;
        *(float4*)(optr + d) = o;
    }
}

} // anonymous namespace

// ---------------------------------------------------------------------------
// kernel_launch: qkv GEMM -> rope/split -> flash attention -> out GEMM
// ---------------------------------------------------------------------------
extern "C" void kernel_launch(void* const* d_in, const int* in_sizes, int n_in,
                              void* d_out, int out_size)
{
    const float* x     = (const float*)d_in[0];
    const float* W_qkv = (const float*)d_in[1];
    const float* b_qkv = (const float*)d_in[2];
    const float* W_out = (const float*)d_in[3];
    const float* b_out = (const float*)d_in[4];
    float* out = (float*)d_out;

    float *qkv, *qp, *kp, *vp, *ctx;
    cudaGetSymbolAddress((void**)&qkv, g_qkv);
    cudaGetSymbolAddress((void**)&qp,  g_q);
    cudaGetSymbolAddress((void**)&kp,  g_k);
    cudaGetSymbolAddress((void**)&vp,  g_v);
    cudaGetSymbolAddress((void**)&ctx, g_ctx);

    // 1) QKV GEMM: [4096,1024] @ [1024,3072] + bias
    {
        dim3 grid(3 * C_ / 128, MTOK / 128);
        sgemm_bias_kernel<<<grid, 256>>>(x, W_qkv, b_qkv, qkv, MTOK, 3 * C_, C_);
    }

    // 2) RoPE + split to [B,H,T,D]
    {
        const int total = B_ * NH * T_ * (HD / 2);  // 2^21
        rope_split_kernel<<<total / 256, 256>>>(qkv, qp, kp, vp);
    }

    // 3) Flash attention -> ctx [B,T,C]
    {
        dim3 grid(T_ / QB, B_ * NH);
        flash_attn_kernel<<<grid, QB>>>(qp, kp, vp, ctx);
    }

    // 4) Output projection: [4096,1024] @ [1024,1024] + bias
    {
        dim3 grid(C_ / 128, MTOK / 128);
        sgemm_bias_kernel<<<grid, 256>>>(ctx, W_out, b_out, out, MTOK, C_, C_);
    }
}

// round 2
// speedup vs baseline: 2.0471x; 2.0471x over previous
#include <cuda_runtime.h>
#include <math.h>
#include <stdint.h>

// ---------------------------------------------------------------------------
// RotarySelfAttention: x[B,T,C] -> QKV GEMM -> RoPE -> attention -> out proj
// B=2, T=2048, C=1024, H=16, D=64
// Round 2: attention moved to tf32 mma.sync tensor cores.
// ---------------------------------------------------------------------------

namespace {

constexpr int B_   = 2;
constexpr int T_   = 2048;
constexpr int C_   = 1024;
constexpr int NH   = 16;
constexpr int HD   = 64;
constexpr int MTOK = B_ * T_;   // 4096

// Scratch (allocation-free rule: __device__ globals)
__device__ float g_qkv[(size_t)MTOK * 3 * C_];     // [B*T, 3C]
__device__ float g_q[(size_t)B_ * NH * T_ * HD];   // [B,H,T,D] (pre-scaled, tf32-rounded)
__device__ float g_k[(size_t)B_ * NH * T_ * HD];   // tf32-rounded
__device__ float g_v[(size_t)B_ * NH * T_ * HD];   // tf32-rounded
__device__ float g_ctx[(size_t)MTOK * C_];         // [B,T,C]

__device__ __forceinline__ float tf32r(float x) {
    uint32_t u;
    asm("cvt.rna.tf32.f32 %0, %1;" : "=r"(u) : "f"(x));
    return __uint_as_float(u);
}

__device__ __forceinline__ void mma_tf32(float c[4], const float a[4], float b0, float b1) {
    asm volatile(
        "mma.sync.aligned.m16n8k8.row.col.f32.tf32.tf32.f32 "
        "{%0,%1,%2,%3}, {%4,%5,%6,%7}, {%8,%9}, {%0,%1,%2,%3};\n"
        : "+f"(c[0]), "+f"(c[1]), "+f"(c[2]), "+f"(c[3])
        : "r"(__float_as_uint(a[0])), "r"(__float_as_uint(a[1])),
          "r"(__float_as_uint(a[2])), "r"(__float_as_uint(a[3])),
          "r"(__float_as_uint(b0)),  "r"(__float_as_uint(b1)));
}

// ---------------------------------------------------------------------------
// SGEMM: C[M,N] = A[M,K] @ B[K,N] + bias[N]   (row-major, dims %128/%8==0)
// ---------------------------------------------------------------------------
__global__ __launch_bounds__(256)
void sgemm_bias_kernel(const float* __restrict__ A,
                       const float* __restrict__ Bm,
                       const float* __restrict__ bias,
                       float* __restrict__ Cout,
                       int M, int N, int K)
{
    constexpr int BM = 128, BN = 128, BK = 8, TM = 8, TN = 8;
    __shared__ float As[BK][BM];
    __shared__ float Bs[BK][BN];

    const int tid  = threadIdx.x;
    const int brow = blockIdx.y * BM;
    const int bcol = blockIdx.x * BN;

    const int aRow = tid >> 1;
    const int aCol = (tid & 1) << 2;
    const int bRow = tid >> 5;
    const int bCol = (tid & 31) << 2;

    const int tRow = (tid >> 4) * TM;
    const int tCol = (tid & 15) * TN;

    float acc[TM][TN];
#pragma unroll
    for (int i = 0; i < TM; i++)
#pragma unroll
        for (int j = 0; j < TN; j++) acc[i][j] = 0.f;

    for (int k0 = 0; k0 < K; k0 += BK) {
        float4 a4 = *(const float4*)(A  + (size_t)(brow + aRow) * K + k0 + aCol);
        float4 b4 = *(const float4*)(Bm + (size_t)(k0 + bRow) * N + bcol + bCol);
        As[aCol + 0][aRow] = a4.x;
        As[aCol + 1][aRow] = a4.y;
        As[aCol + 2][aRow] = a4.z;
        As[aCol + 3][aRow] = a4.w;
        *(float4*)&Bs[bRow][bCol] = b4;
        __syncthreads();

#pragma unroll
        for (int kk = 0; kk < BK; kk++) {
            float ar[TM], br[TN];
#pragma unroll
            for (int i = 0; i < TM; i += 4)
                *(float4*)&ar[i] = *(const float4*)&As[kk][tRow + i];
#pragma unroll
            for (int j = 0; j < TN; j += 4)
                *(float4*)&br[j] = *(const float4*)&Bs[kk][tCol + j];
#pragma unroll
            for (int i = 0; i < TM; i++)
#pragma unroll
                for (int j = 0; j < TN; j++)
                    acc[i][j] += ar[i] * br[j];
        }
        __syncthreads();
    }

#pragma unroll
    for (int i = 0; i < TM; i++) {
        float* crow = Cout + (size_t)(brow + tRow + i) * N + bcol + tCol;
#pragma unroll
        for (int j = 0; j < TN; j += 4) {
            float4 o;
            o.x = acc[i][j + 0] + bias[bcol + tCol + j + 0];
            o.y = acc[i][j + 1] + bias[bcol + tCol + j + 1];
            o.z = acc[i][j + 2] + bias[bcol + tCol + j + 2];
            o.w = acc[i][j + 3] + bias[bcol + tCol + j + 3];
            *(float4*)(crow + j) = o;
        }
    }
}

// ---------------------------------------------------------------------------
// RoPE + split qkv[B*T,3C] -> q,k,v in [B,H,T,D]; outputs tf32-rounded.
// q pre-scaled by D^-0.5.
// ---------------------------------------------------------------------------
__global__ __launch_bounds__(256)
void rope_split_kernel(const float* __restrict__ qkv,
                       float* __restrict__ q,
                       float* __restrict__ k,
                       float* __restrict__ v)
{
    const int idx = blockIdx.x * blockDim.x + threadIdx.x;
    const int d = idx & 31;
    const int t = (idx >> 5) & (T_ - 1);
    const int h = (idx >> 16) & (NH - 1);
    const int b = idx >> 20;

    const float* base = qkv + (size_t)(b * T_ + t) * (3 * C_) + h * HD + d;
    const float q1 = base[0],       q2 = base[32];
    const float k1 = base[C_],      k2 = base[C_ + 32];
    const float v1 = base[2 * C_],  v2 = base[2 * C_ + 32];

    const float inv_freq = expf((float)d * -0.28782313662425574f); // -ln(1e4)/32
    const float ang = (float)t * inv_freq;
    float s, c;
    sincosf(ang, &s, &c);

    const float scale = 0.125f; // HD^-0.5
    const size_t o = ((size_t)(b * NH + h) * T_ + t) * HD + d;
    q[o]      = tf32r((q1 * c - q2 * s) * scale);
    q[o + 32] = tf32r((q2 * c + q1 * s) * scale);
    k[o]      = tf32r(k1 * c - k2 * s);
    k[o + 32] = tf32r(k2 * c + k1 * s);
    v[o]      = tf32r(v1);
    v[o + 32] = tf32r(v2);
}

// ---------------------------------------------------------------------------
// Flash attention, tf32 mma.sync tensor cores, fp32 accumulate.
// Block: 128 threads (4 warps), 64 query rows; KV tiles of 64 keys.
// Warp w owns query rows [16w, 16w+16).
// smem (dynamic, 52 KB): Ks[64][68], Vs[64][72], Ps[64][68]
//   strides chosen so all fragment-load patterns are bank-conflict-free.
// ---------------------------------------------------------------------------
constexpr int QB  = 64;
constexpr int KBt = 64;
constexpr int KS  = 68;  // K / P / Q-stage row stride (floats)
constexpr int VS  = 72;  // V row stride (floats)
constexpr int SMEM_FLOATS = KBt * KS + KBt * VS + QB * KS; // 13312
constexpr int SMEM_BYTES  = SMEM_FLOATS * 4;               // 53248

__global__ __launch_bounds__(128)
void flash_attn_tf32_kernel(const float* __restrict__ q,
                            const float* __restrict__ k,
                            const float* __restrict__ v,
                            float* __restrict__ ctx)
{
    extern __shared__ float sm[];
    float* Ks = sm;                       // [64][68]
    float* Vs = sm + KBt * KS;            // [64][72]
    float* Ps = sm + KBt * KS + KBt * VS; // [64][68]  (Q stage, then P)

    const int tid  = threadIdx.x;
    const int lane = tid & 31;
    const int wid  = tid >> 5;
    const int bh   = blockIdx.y;          // b*NH + h
    const int b    = bh >> 4;
    const int h    = bh & 15;
    const int q0   = blockIdx.x * QB;

    const int lq = lane >> 2;             // lane group id (0..7)
    const int lr = lane & 3;              // lane in group  (0..3)
    const int r0 = wid * 16 + lq;         // first query row owned

    const float NEG_INF = __int_as_float(0xff800000u);

    // ---- stage Q tile into Ps, pull A-fragments into registers ----
    const float* qbase = q + ((size_t)bh * T_ + q0) * HD;
#pragma unroll
    for (int i = tid; i < QB * 16; i += 128) {
        const int row = i >> 4, c4 = i & 15;
        *(float4*)&Ps[row * KS + c4 * 4] = *(const float4*)&qbase[(size_t)row * HD + c4 * 4];
    }
    __syncthreads();

    float qf[8][4];   // A frags: 8 k-steps over D
#pragma unroll
    for (int kk = 0; kk < 8; kk++) {
        const int c = kk * 8 + lr;
        qf[kk][0] = Ps[r0 * KS + c];
        qf[kk][1] = Ps[(r0 + 8) * KS + c];
        qf[kk][2] = Ps[r0 * KS + c + 4];
        qf[kk][3] = Ps[(r0 + 8) * KS + c + 4];
    }

    float oacc[8][4];
#pragma unroll
    for (int n = 0; n < 8; n++)
#pragma unroll
        for (int j = 0; j < 4; j++) oacc[n][j] = 0.f;
    float m0 = NEG_INF, m1 = NEG_INF, l0 = 0.f, l1 = 0.f;

    const float* kb = k + (size_t)bh * T_ * HD;
    const float* vb = v + (size_t)bh * T_ * HD;

    for (int kt = 0; kt < T_; kt += KBt) {
        __syncthreads();   // previous tile (incl. Ps as P) fully consumed
        // ---- load K/V tiles ----
#pragma unroll
        for (int i = tid; i < KBt * 16; i += 128) {
            const int row = i >> 4, c4 = i & 15;
            *(float4*)&Ks[row * KS + c4 * 4] = *(const float4*)&kb[(size_t)(kt + row) * HD + c4 * 4];
            *(float4*)&Vs[row * VS + c4 * 4] = *(const float4*)&vb[(size_t)(kt + row) * HD + c4 * 4];
        }
        __syncthreads();

        // ---- S = Q K^T  (16 rows x 64 keys per warp) ----
        float sacc[8][4];
#pragma unroll
        for (int n = 0; n < 8; n++)
#pragma unroll
            for (int j = 0; j < 4; j++) sacc[n][j] = 0.f;

#pragma unroll
        for (int kk = 0; kk < 8; kk++) {
#pragma unroll
            for (int n = 0; n < 8; n++) {
                const float b0 = Ks[(n * 8 + lq) * KS + kk * 8 + lr];
                const float b1 = Ks[(n * 8 + lq) * KS + kk * 8 + lr + 4];
                mma_tf32(sacc[n], qf[kk], b0, b1);
            }
        }

        // ---- online softmax ----
        float tm0 = NEG_INF, tm1 = NEG_INF;
#pragma unroll
        for (int n = 0; n < 8; n++) {
            tm0 = fmaxf(tm0, fmaxf(sacc[n][0], sacc[n][1]));
            tm1 = fmaxf(tm1, fmaxf(sacc[n][2], sacc[n][3]));
        }
        tm0 = fmaxf(tm0, __shfl_xor_sync(0xffffffffu, tm0, 1));
        tm0 = fmaxf(tm0, __shfl_xor_sync(0xffffffffu, tm0, 2));
        tm1 = fmaxf(tm1, __shfl_xor_sync(0xffffffffu, tm1, 1));
        tm1 = fmaxf(tm1, __shfl_xor_sync(0xffffffffu, tm1, 2));

        const float mn0 = fmaxf(m0, tm0), mn1 = fmaxf(m1, tm1);
        const float a0 = __expf(m0 - mn0), a1 = __expf(m1 - mn1);
        l0 *= a0; l1 *= a1;
#pragma unroll
        for (int n = 0; n < 8; n++) {
            oacc[n][0] *= a0; oacc[n][1] *= a0;
            oacc[n][2] *= a1; oacc[n][3] *= a1;
        }
        m0 = mn0; m1 = mn1;

        // ---- P = exp(S - m), tf32-rounded, to warp-private Ps rows ----
#pragma unroll
        for (int n = 0; n < 8; n++) {
            const float p0 = __expf(sacc[n][0] - mn0);
            const float p1 = __expf(sacc[n][1] - mn0);
            const float p2 = __expf(sacc[n][2] - mn1);
            const float p3 = __expf(sacc[n][3] - mn1);
            l0 += p0 + p1; l1 += p2 + p3;
            float2 s01, s23;
            s01.x = tf32r(p0); s01.y = tf32r(p1);
            s23.x = tf32r(p2); s23.y = tf32r(p3);
            *(float2*)&Ps[r0 * KS + n * 8 + lr * 2]       = s01;
            *(float2*)&Ps[(r0 + 8) * KS + n * 8 + lr * 2] = s23;
        }
        __syncwarp();

        // ---- O += P V ----
#pragma unroll
        for (int kk = 0; kk < 8; kk++) {
            float af[4];
            af[0] = Ps[r0 * KS + kk * 8 + lr];
            af[1] = Ps[(r0 + 8) * KS + kk * 8 + lr];
            af[2] = Ps[r0 * KS + kk * 8 + lr + 4];
            af[3] = Ps[(r0 + 8) * KS + kk * 8 + lr + 4];
#pragma unroll
            for (int n = 0; n < 8; n++) {
                const float b0 = Vs[(kk * 8 + lr) * VS + n * 8 + lq];
                const float b1 = Vs[(kk * 8 + lr + 4) * VS + n * 8 + lq];
                mma_tf32(oacc[n], af, b0, b1);
            }
        }
    }

    // ---- epilogue: normalize, write ctx[B,T,C] ----
    l0 += __shfl_xor_sync(0xffffffffu, l0, 1);
    l0 += __shfl_xor_sync(0xffffffffu, l0, 2);
    l1 += __shfl_xor_sync(0xffffffffu, l1, 1);
    l1 += __shfl_xor_sync(0xffffffffu, l1, 2);
    const float inv0 = 1.f / l0, inv1 = 1.f / l1;

    float* ob0 = ctx + ((size_t)(b * T_) + q0 + r0) * C_ + h * HD;
    float* ob1 = ob0 + (size_t)8 * C_;
#pragma unroll
    for (int n = 0; n < 8; n++) {
        float2 w0, w1;
        w0.x = oacc[n][0] * inv0; w0.y = oacc[n][1] * inv0;
        w1.x = oacc[n][2] * inv1; w1.y = oacc[n][3] * inv1;
        *(float2*)&ob0[n * 8 + lr * 2] = w0;
        *(float2*)&ob1[n * 8 + lr * 2] = w1;
    }
}

} // anonymous namespace

// ---------------------------------------------------------------------------
extern "C" void kernel_launch(void* const* d_in, const int* in_sizes, int n_in,
                              void* d_out, int out_size)
{
    const float* x     = (const float*)d_in[0];
    const float* W_qkv = (const float*)d_in[1];
    const float* b_qkv = (const float*)d_in[2];
    const float* W_out = (const float*)d_in[3];
    const float* b_out = (const float*)d_in[4];
    float* out = (float*)d_out;

    float *qkv, *qp, *kp, *vp, *ctx;
    cudaGetSymbolAddress((void**)&qkv, g_qkv);
    cudaGetSymbolAddress((void**)&qp,  g_q);
    cudaGetSymbolAddress((void**)&kp,  g_k);
    cudaGetSymbolAddress((void**)&vp,  g_v);
    cudaGetSymbolAddress((void**)&ctx, g_ctx);

    // 1) QKV GEMM
    {
        dim3 grid(3 * C_ / 128, MTOK / 128);
        sgemm_bias_kernel<<<grid, 256>>>(x, W_qkv, b_qkv, qkv, MTOK, 3 * C_, C_);
    }

    // 2) RoPE + split (tf32-rounded outputs)
    {
        const int total = B_ * NH * T_ * (HD / 2);
        rope_split_kernel<<<total / 256, 256>>>(qkv, qp, kp, vp);
    }

    // 3) Flash attention (tf32 tensor cores)
    {
        cudaFuncSetAttribute(flash_attn_tf32_kernel,
                             cudaFuncAttributeMaxDynamicSharedMemorySize, SMEM_BYTES);
        dim3 grid(T_ / QB, B_ * NH);
        flash_attn_tf32_kernel<<<grid, 128, SMEM_BYTES>>>(qp, kp, vp, ctx);
    }

    // 4) Output projection
    {
        dim3 grid(C_ / 128, MTOK / 128);
        sgemm_bias_kernel<<<grid, 256>>>(ctx, W_out, b_out, out, MTOK, C_, C_);
    }
}

// round 3
// speedup vs baseline: 4.2879x; 2.0946x over previous
#include <cuda_runtime.h>
#include <math.h>
#include <stdint.h>

// ---------------------------------------------------------------------------
// RotarySelfAttention: x[B,T,C] -> QKV GEMM -> RoPE -> attention -> out proj
// B=2, T=2048, C=1024, H=16, D=64
// Round 3: GEMMs moved to tf32 mma.sync tensor cores as well.
// ---------------------------------------------------------------------------

namespace {

constexpr int B_   = 2;
constexpr int T_   = 2048;
constexpr int C_   = 1024;
constexpr int NH   = 16;
constexpr int HD   = 64;
constexpr int MTOK = B_ * T_;   // 4096

// Scratch (allocation-free rule: __device__ globals)
__device__ float g_qkv[(size_t)MTOK * 3 * C_];     // [B*T, 3C]
__device__ float g_q[(size_t)B_ * NH * T_ * HD];   // [B,H,T,D] (pre-scaled, tf32-rounded)
__device__ float g_k[(size_t)B_ * NH * T_ * HD];   // tf32-rounded
__device__ float g_v[(size_t)B_ * NH * T_ * HD];   // tf32-rounded
__device__ float g_ctx[(size_t)MTOK * C_];         // [B,T,C]

__device__ __forceinline__ float tf32r(float x) {
    uint32_t u;
    asm("cvt.rna.tf32.f32 %0, %1;" : "=r"(u) : "f"(x));
    return __uint_as_float(u);
}

__device__ __forceinline__ void mma_tf32(float c[4], const float a[4], float b0, float b1) {
    asm volatile(
        "mma.sync.aligned.m16n8k8.row.col.f32.tf32.tf32.f32 "
        "{%0,%1,%2,%3}, {%4,%5,%6,%7}, {%8,%9}, {%0,%1,%2,%3};\n"
        : "+f"(c[0]), "+f"(c[1]), "+f"(c[2]), "+f"(c[3])
        : "r"(__float_as_uint(a[0])), "r"(__float_as_uint(a[1])),
          "r"(__float_as_uint(a[2])), "r"(__float_as_uint(a[3])),
          "r"(__float_as_uint(b0)),  "r"(__float_as_uint(b1)));
}

// ---------------------------------------------------------------------------
// tf32 tensor-core GEMM: C[M,N] = A[M,K] @ B[K,N] + bias[N]
// Block 128x128x16, 128 threads = 4 warps (2x2), warp tile 64x64.
// As[128][20]: [m][k], pad 20 -> frag loads hit 32 distinct banks.
// Bs[16][136]: [k][n], stride 136 (== 8 mod 32) -> conflict-free frags,
//              coalesced float4 copy-in.
// ---------------------------------------------------------------------------
constexpr int GAS = 20;    // As row stride (floats)
constexpr int GBS = 136;   // Bs row stride (floats)

__global__ __launch_bounds__(128)
void gemm_tf32_bias(const float* __restrict__ A,
                    const float* __restrict__ Bm,
                    const float* __restrict__ bias,
                    float* __restrict__ Cout,
                    int M, int N, int K)
{
    __shared__ float As[128 * GAS];   // [m][k]
    __shared__ float Bs[16 * GBS];    // [k][n]

    const int tid  = threadIdx.x;
    const int lane = tid & 31;
    const int wid  = tid >> 5;
    const int lq   = lane >> 2;
    const int lr   = lane & 3;

    const int brow = blockIdx.y * 128;
    const int bcol = blockIdx.x * 128;
    const int wm   = (wid & 1) * 64;
    const int wn   = (wid >> 1) * 64;

    // global->reg load mappings
    const int aRow = tid >> 2;          // 0..31 (+p*32)
    const int aCol = (tid & 3) * 4;     // 0,4,8,12
    const int bRow = tid >> 3;          // 0..15
    const int bCol = (tid & 7) * 4;     // 0..28 (+j*32)

    float acc[4][8][4];
#pragma unroll
    for (int i = 0; i < 4; i++)
#pragma unroll
        for (int j = 0; j < 8; j++)
#pragma unroll
            for (int t = 0; t < 4; t++) acc[i][j][t] = 0.f;

    float4 ar[4], br[4];
    // prefetch tile 0
#pragma unroll
    for (int p = 0; p < 4; p++)
        ar[p] = *(const float4*)&A[(size_t)(brow + aRow + p * 32) * K + aCol];
#pragma unroll
    for (int j = 0; j < 4; j++)
        br[j] = *(const float4*)&Bm[(size_t)bRow * N + bcol + bCol + j * 32];

    for (int k0 = 0; k0 < K; k0 += 16) {
        // store prefetched regs to smem (tf32-rounded)
#pragma unroll
        for (int p = 0; p < 4; p++) {
            float4 t4 = ar[p];
            t4.x = tf32r(t4.x); t4.y = tf32r(t4.y);
            t4.z = tf32r(t4.z); t4.w = tf32r(t4.w);
            *(float4*)&As[(aRow + p * 32) * GAS + aCol] = t4;
        }
#pragma unroll
        for (int j = 0; j < 4; j++) {
            float4 t4 = br[j];
            t4.x = tf32r(t4.x); t4.y = tf32r(t4.y);
            t4.z = tf32r(t4.z); t4.w = tf32r(t4.w);
            *(float4*)&Bs[bRow * GBS + bCol + j * 32] = t4;
        }
        __syncthreads();

        // prefetch next tile
        if (k0 + 16 < K) {
#pragma unroll
            for (int p = 0; p < 4; p++)
                ar[p] = *(const float4*)&A[(size_t)(brow + aRow + p * 32) * K + k0 + 16 + aCol];
#pragma unroll
            for (int j = 0; j < 4; j++)
                br[j] = *(const float4*)&Bm[(size_t)(k0 + 16 + bRow) * N + bcol + bCol + j * 32];
        }

        // compute: 2 k-steps of 8
#pragma unroll
        for (int kk = 0; kk < 16; kk += 8) {
            float a[4][4];
#pragma unroll
            for (int i = 0; i < 4; i++) {
                const int m = wm + i * 16 + lq;
                a[i][0] = As[m * GAS + kk + lr];
                a[i][1] = As[(m + 8) * GAS + kk + lr];
                a[i][2] = As[m * GAS + kk + lr + 4];
                a[i][3] = As[(m + 8) * GAS + kk + lr + 4];
            }
#pragma unroll
            for (int j = 0; j < 8; j++) {
                const int n = wn + j * 8 + lq;
                const float b0 = Bs[(kk + lr) * GBS + n];
                const float b1 = Bs[(kk + lr + 4) * GBS + n];
#pragma unroll
                for (int i = 0; i < 4; i++)
                    mma_tf32(acc[i][j], a[i], b0, b1);
            }
        }
        __syncthreads();
    }

    // epilogue: + bias, write fp32
#pragma unroll
    for (int i = 0; i < 4; i++) {
        const int row0 = brow + wm + i * 16 + lq;
#pragma unroll
        for (int j = 0; j < 8; j++) {
            const int col = bcol + wn + j * 8 + lr * 2;
            const float bi0 = bias[col], bi1 = bias[col + 1];
            float2 w0, w1;
            w0.x = acc[i][j][0] + bi0; w0.y = acc[i][j][1] + bi1;
            w1.x = acc[i][j][2] + bi0; w1.y = acc[i][j][3] + bi1;
            *(float2*)&Cout[(size_t)row0 * N + col]       = w0;
            *(float2*)&Cout[(size_t)(row0 + 8) * N + col] = w1;
        }
    }
}

// ---------------------------------------------------------------------------
// RoPE + split qkv[B*T,3C] -> q,k,v in [B,H,T,D]; outputs tf32-rounded.
// q pre-scaled by D^-0.5.
// ---------------------------------------------------------------------------
__global__ __launch_bounds__(256)
void rope_split_kernel(const float* __restrict__ qkv,
                       float* __restrict__ q,
                       float* __restrict__ k,
                       float* __restrict__ v)
{
    const int idx = blockIdx.x * blockDim.x + threadIdx.x;
    const int d = idx & 31;
    const int t = (idx >> 5) & (T_ - 1);
    const int h = (idx >> 16) & (NH - 1);
    const int b = idx >> 20;

    const float* base = qkv + (size_t)(b * T_ + t) * (3 * C_) + h * HD + d;
    const float q1 = base[0],       q2 = base[32];
    const float k1 = base[C_],      k2 = base[C_ + 32];
    const float v1 = base[2 * C_],  v2 = base[2 * C_ + 32];

    const float inv_freq = expf((float)d * -0.28782313662425574f); // -ln(1e4)/32
    const float ang = (float)t * inv_freq;
    float s, c;
    sincosf(ang, &s, &c);

    const float scale = 0.125f; // HD^-0.5
    const size_t o = ((size_t)(b * NH + h) * T_ + t) * HD + d;
    q[o]      = tf32r((q1 * c - q2 * s) * scale);
    q[o + 32] = tf32r((q2 * c + q1 * s) * scale);
    k[o]      = tf32r(k1 * c - k2 * s);
    k[o + 32] = tf32r(k2 * c + k1 * s);
    v[o]      = tf32r(v1);
    v[o + 32] = tf32r(v2);
}

// ---------------------------------------------------------------------------
// Flash attention, tf32 mma.sync tensor cores, fp32 accumulate.
// Block: 128 threads (4 warps), 64 query rows; KV tiles of 64 keys.
// ---------------------------------------------------------------------------
constexpr int QB  = 64;
constexpr int KBt = 64;
constexpr int KS  = 68;  // K / P / Q-stage row stride (floats)
constexpr int VS  = 72;  // V row stride (floats)
constexpr int SMEM_FLOATS = KBt * KS + KBt * VS + QB * KS; // 13312
constexpr int SMEM_BYTES  = SMEM_FLOATS * 4;               // 53248

__global__ __launch_bounds__(128)
void flash_attn_tf32_kernel(const float* __restrict__ q,
                            const float* __restrict__ k,
                            const float* __restrict__ v,
                            float* __restrict__ ctx)
{
    extern __shared__ float sm[];
    float* Ks = sm;                       // [64][68]
    float* Vs = sm + KBt * KS;            // [64][72]
    float* Ps = sm + KBt * KS + KBt * VS; // [64][68]  (Q stage, then P)

    const int tid  = threadIdx.x;
    const int lane = tid & 31;
    const int wid  = tid >> 5;
    const int bh   = blockIdx.y;          // b*NH + h
    const int b    = bh >> 4;
    const int h    = bh & 15;
    const int q0   = blockIdx.x * QB;

    const int lq = lane >> 2;
    const int lr = lane & 3;
    const int r0 = wid * 16 + lq;

    const float NEG_INF = __int_as_float(0xff800000u);

    // ---- stage Q tile into Ps, pull A-fragments into registers ----
    const float* qbase = q + ((size_t)bh * T_ + q0) * HD;
#pragma unroll
    for (int i = tid; i < QB * 16; i += 128) {
        const int row = i >> 4, c4 = i & 15;
        *(float4*)&Ps[row * KS + c4 * 4] = *(const float4*)&qbase[(size_t)row * HD + c4 * 4];
    }
    __syncthreads();

    float qf[8][4];
#pragma unroll
    for (int kk = 0; kk < 8; kk++) {
        const int c = kk * 8 + lr;
        qf[kk][0] = Ps[r0 * KS + c];
        qf[kk][1] = Ps[(r0 + 8) * KS + c];
        qf[kk][2] = Ps[r0 * KS + c + 4];
        qf[kk][3] = Ps[(r0 + 8) * KS + c + 4];
    }

    float oacc[8][4];
#pragma unroll
    for (int n = 0; n < 8; n++)
#pragma unroll
        for (int j = 0; j < 4; j++) oacc[n][j] = 0.f;
    float m0 = NEG_INF, m1 = NEG_INF, l0 = 0.f, l1 = 0.f;

    const float* kb = k + (size_t)bh * T_ * HD;
    const float* vb = v + (size_t)bh * T_ * HD;

    for (int kt = 0; kt < T_; kt += KBt) {
        __syncthreads();
#pragma unroll
        for (int i = tid; i < KBt * 16; i += 128) {
            const int row = i >> 4, c4 = i & 15;
            *(float4*)&Ks[row * KS + c4 * 4] = *(const float4*)&kb[(size_t)(kt + row) * HD + c4 * 4];
            *(float4*)&Vs[row * VS + c4 * 4] = *(const float4*)&vb[(size_t)(kt + row) * HD + c4 * 4];
        }
        __syncthreads();

        // ---- S = Q K^T ----
        float sacc[8][4];
#pragma unroll
        for (int n = 0; n < 8; n++)
#pragma unroll
            for (int j = 0; j < 4; j++) sacc[n][j] = 0.f;

#pragma unroll
        for (int kk = 0; kk < 8; kk++) {
#pragma unroll
            for (int n = 0; n < 8; n++) {
                const float b0 = Ks[(n * 8 + lq) * KS + kk * 8 + lr];
                const float b1 = Ks[(n * 8 + lq) * KS + kk * 8 + lr + 4];
                mma_tf32(sacc[n], qf[kk], b0, b1);
            }
        }

        // ---- online softmax ----
        float tm0 = NEG_INF, tm1 = NEG_INF;
#pragma unroll
        for (int n = 0; n < 8; n++) {
            tm0 = fmaxf(tm0, fmaxf(sacc[n][0], sacc[n][1]));
            tm1 = fmaxf(tm1, fmaxf(sacc[n][2], sacc[n][3]));
        }
        tm0 = fmaxf(tm0, __shfl_xor_sync(0xffffffffu, tm0, 1));
        tm0 = fmaxf(tm0, __shfl_xor_sync(0xffffffffu, tm0, 2));
        tm1 = fmaxf(tm1, __shfl_xor_sync(0xffffffffu, tm1, 1));
        tm1 = fmaxf(tm1, __shfl_xor_sync(0xffffffffu, tm1, 2));

        const float mn0 = fmaxf(m0, tm0), mn1 = fmaxf(m1, tm1);
        const float a0 = __expf(m0 - mn0), a1 = __expf(m1 - mn1);
        l0 *= a0; l1 *= a1;
#pragma unroll
        for (int n = 0; n < 8; n++) {
            oacc[n][0] *= a0; oacc[n][1] *= a0;
            oacc[n][2] *= a1; oacc[n][3] *= a1;
        }
        m0 = mn0; m1 = mn1;

        // ---- P = exp(S - m), tf32-rounded, warp-private Ps rows ----
#pragma unroll
        for (int n = 0; n < 8; n++) {
            const float p0 = __expf(sacc[n][0] - mn0);
            const float p1 = __expf(sacc[n][1] - mn0);
            const float p2 = __expf(sacc[n][2] - mn1);
            const float p3 = __expf(sacc[n][3] - mn1);
            l0 += p0 + p1; l1 += p2 + p3;
            float2 s01, s23;
            s01.x = tf32r(p0); s01.y = tf32r(p1);
            s23.x = tf32r(p2); s23.y = tf32r(p3);
            *(float2*)&Ps[r0 * KS + n * 8 + lr * 2]       = s01;
            *(float2*)&Ps[(r0 + 8) * KS + n * 8 + lr * 2] = s23;
        }
        __syncwarp();

        // ---- O += P V ----
#pragma unroll
        for (int kk = 0; kk < 8; kk++) {
            float af[4];
            af[0] = Ps[r0 * KS + kk * 8 + lr];
            af[1] = Ps[(r0 + 8) * KS + kk * 8 + lr];
            af[2] = Ps[r0 * KS + kk * 8 + lr + 4];
            af[3] = Ps[(r0 + 8) * KS + kk * 8 + lr + 4];
#pragma unroll
            for (int n = 0; n < 8; n++) {
                const float b0 = Vs[(kk * 8 + lr) * VS + n * 8 + lq];
                const float b1 = Vs[(kk * 8 + lr + 4) * VS + n * 8 + lq];
                mma_tf32(oacc[n], af, b0, b1);
            }
        }
    }

    // ---- epilogue ----
    l0 += __shfl_xor_sync(0xffffffffu, l0, 1);
    l0 += __shfl_xor_sync(0xffffffffu, l0, 2);
    l1 += __shfl_xor_sync(0xffffffffu, l1, 1);
    l1 += __shfl_xor_sync(0xffffffffu, l1, 2);
    const float inv0 = 1.f / l0, inv1 = 1.f / l1;

    float* ob0 = ctx + ((size_t)(b * T_) + q0 + r0) * C_ + h * HD;
    float* ob1 = ob0 + (size_t)8 * C_;
#pragma unroll
    for (int n = 0; n < 8; n++) {
        float2 w0, w1;
        w0.x = oacc[n][0] * inv0; w0.y = oacc[n][1] * inv0;
        w1.x = oacc[n][2] * inv1; w1.y = oacc[n][3] * inv1;
        *(float2*)&ob0[n * 8 + lr * 2] = w0;
        *(float2*)&ob1[n * 8 + lr * 2] = w1;
    }
}

} // anonymous namespace

// ---------------------------------------------------------------------------
extern "C" void kernel_launch(void* const* d_in, const int* in_sizes, int n_in,
                              void* d_out, int out_size)
{
    const float* x     = (const float*)d_in[0];
    const float* W_qkv = (const float*)d_in[1];
    const float* b_qkv = (const float*)d_in[2];
    const float* W_out = (const float*)d_in[3];
    const float* b_out = (const float*)d_in[4];
    float* out = (float*)d_out;

    float *qkv, *qp, *kp, *vp, *ctx;
    cudaGetSymbolAddress((void**)&qkv, g_qkv);
    cudaGetSymbolAddress((void**)&qp,  g_q);
    cudaGetSymbolAddress((void**)&kp,  g_k);
    cudaGetSymbolAddress((void**)&vp,  g_v);
    cudaGetSymbolAddress((void**)&ctx, g_ctx);

    // 1) QKV GEMM (tf32 tensor cores)
    {
        dim3 grid(3 * C_ / 128, MTOK / 128);
        gemm_tf32_bias<<<grid, 128>>>(x, W_qkv, b_qkv, qkv, MTOK, 3 * C_, C_);
    }

    // 2) RoPE + split (tf32-rounded outputs)
    {
        const int total = B_ * NH * T_ * (HD / 2);
        rope_split_kernel<<<total / 256, 256>>>(qkv, qp, kp, vp);
    }

    // 3) Flash attention (tf32 tensor cores)
    {
        cudaFuncSetAttribute(flash_attn_tf32_kernel,
                             cudaFuncAttributeMaxDynamicSharedMemorySize, SMEM_BYTES);
        dim3 grid(T_ / QB, B_ * NH);
        flash_attn_tf32_kernel<<<grid, 128, SMEM_BYTES>>>(qp, kp, vp, ctx);
    }

    // 4) Output projection (tf32 tensor cores)
    {
        dim3 grid(C_ / 128, MTOK / 128);
        gemm_tf32_bias<<<grid, 128>>>(ctx, W_out, b_out, out, MTOK, C_, C_);
    }
}